// round 1
// baseline (speedup 1.0000x reference)
#include <cuda_runtime.h>
#include <cstdint>

#define B_   8192
#define IN_  2048
#define OUT_ 3072
#define S_   8

#define TM 128
#define TN 128
#define TK 16

// Scratch (no cudaMalloc allowed): bucketed row indices per subject.
__device__ int g_bucket[S_][B_];
__device__ int g_count[S_];
__device__ int g_is64;

__global__ void k_init() {
    if (threadIdx.x < S_) g_count[threadIdx.x] = 0;
    if (threadIdx.x == 0) g_is64 = 1;
}

// subject_ids may be int32 or int64 depending on JAX x64 config.
// If int64 (little-endian, values 0..7), every odd 32-bit word is 0.
// If int32 with 8192 random ids in [0,8), some odd word is nonzero w.p. ~1.
__global__ void k_detect(const int* __restrict__ sid32) {
    int i = blockIdx.x * blockDim.x + threadIdx.x;
    if (i < B_ / 2) {
        if (sid32[2 * i + 1] != 0) g_is64 = 0;  // benign race, all writers store 0
    }
}

__global__ void k_bucket(const int* __restrict__ sid32) {
    int b = blockIdx.x * blockDim.x + threadIdx.x;
    if (b >= B_) return;
    int s = g_is64 ? sid32[2 * b] : sid32[b];
    int pos = atomicAdd(&g_count[s], 1);
    g_bucket[s][pos] = b;
}

// Classic 128x128x16 register-tiled SGEMM, rows gathered per subject.
// grid = (OUT/TN, ceil(B/TM), S); blocks whose row tile exceeds the
// subject's row count exit immediately.
__global__ __launch_bounds__(256, 2)
void k_gemm(const float* __restrict__ x, const float* __restrict__ w,
            const float* __restrict__ bias, float* __restrict__ out) {
    const int s    = blockIdx.z;
    const int cnt  = g_count[s];
    const int row0 = blockIdx.y * TM;
    if (row0 >= cnt) return;
    const int col0 = blockIdx.x * TN;

    __shared__ float As[TK][TM];
    __shared__ float Bs[TK][TN];
    __shared__ int   rows[TM];

    const int tid = threadIdx.x;
    if (tid < TM) {
        int r = row0 + tid;
        rows[tid] = (r < cnt) ? g_bucket[s][r] : -1;
    }
    __syncthreads();

    const float* W = w + (size_t)s * IN_ * OUT_;

    float acc[8][8];
#pragma unroll
    for (int i = 0; i < 8; i++)
#pragma unroll
        for (int j = 0; j < 8; j++) acc[i][j] = 0.f;

    const int tx = tid & 15;   // 0..15 -> 8 output cols each
    const int ty = tid >> 4;   // 0..15 -> 8 output rows each

    for (int k0 = 0; k0 < IN_; k0 += TK) {
        // ---- load A tile: 128 rows x 16 k (gathered rows), store transposed As[k][m]
#pragma unroll
        for (int l = 0; l < 2; l++) {
            int slot = tid + l * 256;      // 0..511
            int ar   = slot >> 2;          // 0..127 (tile row)
            int k4   = slot & 3;           // 0..3 (float4 index along k)
            int grow = rows[ar];
            float4 v = make_float4(0.f, 0.f, 0.f, 0.f);
            if (grow >= 0)
                v = *(const float4*)(x + (size_t)grow * IN_ + k0 + k4 * 4);
            As[k4 * 4 + 0][ar] = v.x;
            As[k4 * 4 + 1][ar] = v.y;
            As[k4 * 4 + 2][ar] = v.z;
            As[k4 * 4 + 3][ar] = v.w;
        }
        // ---- load B tile: W[k0+kk][col0 + c], 16 x 128, coalesced float4
#pragma unroll
        for (int l = 0; l < 2; l++) {
            int slot = tid + l * 256;      // 0..511
            int kk   = slot >> 5;          // 0..15
            int c4   = slot & 31;          // 0..31
            float4 v = *(const float4*)(W + (size_t)(k0 + kk) * OUT_ + col0 + c4 * 4);
            *(float4*)&Bs[kk][c4 * 4] = v;
        }
        __syncthreads();

#pragma unroll
        for (int kk = 0; kk < TK; kk++) {
            float a[8], b[8];
            *(float4*)&a[0] = *(const float4*)&As[kk][ty * 8];
            *(float4*)&a[4] = *(const float4*)&As[kk][ty * 8 + 4];
            *(float4*)&b[0] = *(const float4*)&Bs[kk][tx * 8];
            *(float4*)&b[4] = *(const float4*)&Bs[kk][tx * 8 + 4];
#pragma unroll
            for (int i = 0; i < 8; i++)
#pragma unroll
                for (int j = 0; j < 8; j++)
                    acc[i][j] += a[i] * b[j];
        }
        __syncthreads();
    }

    // ---- epilogue: out[row][n] = acc + bias[s][n]
    const float* bb = bias + s * OUT_ + col0 + tx * 8;
    float bv[8];
#pragma unroll
    for (int j = 0; j < 8; j++) bv[j] = bb[j];

#pragma unroll
    for (int i = 0; i < 8; i++) {
        int ar   = ty * 8 + i;
        int grow = rows[ar];
        if (grow < 0) continue;
        float* o = out + (size_t)grow * OUT_ + col0 + tx * 8;
        float4 v0 = make_float4(acc[i][0] + bv[0], acc[i][1] + bv[1],
                                acc[i][2] + bv[2], acc[i][3] + bv[3]);
        float4 v1 = make_float4(acc[i][4] + bv[4], acc[i][5] + bv[5],
                                acc[i][6] + bv[6], acc[i][7] + bv[7]);
        *(float4*)(o)     = v0;
        *(float4*)(o + 4) = v1;
    }
}

extern "C" void kernel_launch(void* const* d_in, const int* in_sizes, int n_in,
                              void* d_out, int out_size) {
    const float* x    = (const float*)d_in[0];
    const int*   sid  = (const int*)d_in[1];   // int32 view; detector handles int64
    const float* w    = (const float*)d_in[2];
    const float* bias = (const float*)d_in[3];
    float*       out  = (float*)d_out;

    k_init<<<1, 32>>>();
    k_detect<<<(B_ / 2 + 255) / 256, 256>>>(sid);
    k_bucket<<<(B_ + 255) / 256, 256>>>(sid);

    dim3 grid(OUT_ / TN, B_ / TM, S_);
    k_gemm<<<grid, 256>>>(x, w, bias, out);
}

// round 5
// speedup vs baseline: 2.8614x; 2.8614x over previous
#include <cuda_runtime.h>
#include <cuda_bf16.h>
#include <cstdint>

#define B_   8192
#define IN_  2048
#define OUT_ 3072
#define S_   8

#define TM 128
#define TN 128
#define TK 32
#define NST (IN_ / TK)   // 64 K-stages

// ---------------- scratch (device globals; no cudaMalloc allowed) -----------
__device__ int g_bucket[S_][B_];
__device__ int g_count[S_];
__device__ int g_is64;

__device__ __nv_bfloat16 g_xhi[(size_t)B_ * IN_];
__device__ __nv_bfloat16 g_xlo[(size_t)B_ * IN_];
__device__ __nv_bfloat16 g_whi[(size_t)S_ * IN_ * OUT_];   // same [s][k][o] layout
__device__ __nv_bfloat16 g_wlo[(size_t)S_ * IN_ * OUT_];

// ---------------- helpers ----------------------------------------------------
__device__ __forceinline__ uint32_t smem_u32(const void* p) {
    uint32_t a;
    asm("{ .reg .u64 t; cvta.to.shared.u64 t, %1; cvt.u32.u64 %0, t; }"
        : "=r"(a) : "l"(p));
    return a;
}

__device__ __forceinline__ void cpasync16(uint32_t s, const void* g) {
    asm volatile("cp.async.cg.shared.global [%0], [%1], 16;"
                 :: "r"(s), "l"(g) : "memory");
}
#define CP_COMMIT() asm volatile("cp.async.commit_group;" ::: "memory")
#define CP_WAIT1()  asm volatile("cp.async.wait_group 1;"  ::: "memory")

#define LDSM_X4(r, a)                                                        \
    asm volatile("ldmatrix.sync.aligned.m8n8.x4.shared.b16 {%0,%1,%2,%3}, [%4];" \
                 : "=r"((r)[0]), "=r"((r)[1]), "=r"((r)[2]), "=r"((r)[3])    \
                 : "r"(a))
#define LDSM_X4_T(r, a)                                                      \
    asm volatile("ldmatrix.sync.aligned.m8n8.x4.trans.shared.b16 {%0,%1,%2,%3}, [%4];" \
                 : "=r"((r)[0]), "=r"((r)[1]), "=r"((r)[2]), "=r"((r)[3])    \
                 : "r"(a))

#define MMA16816(d, a, b0, b1)                                               \
    asm volatile("mma.sync.aligned.m16n8k16.row.col.f32.bf16.bf16.f32 "      \
                 "{%0,%1,%2,%3}, {%4,%5,%6,%7}, {%8,%9}, {%0,%1,%2,%3};"     \
                 : "+f"((d)[0]), "+f"((d)[1]), "+f"((d)[2]), "+f"((d)[3])    \
                 : "r"((a)[0]), "r"((a)[1]), "r"((a)[2]), "r"((a)[3]),       \
                   "r"(b0), "r"(b1))

// ---------------- prologue kernels -------------------------------------------
__global__ void k_init() {
    if (threadIdx.x < S_) g_count[threadIdx.x] = 0;
    if (threadIdx.x == 0) g_is64 = 1;
}
__global__ void k_detect(const int* __restrict__ sid32) {
    int i = blockIdx.x * blockDim.x + threadIdx.x;
    if (i < B_ / 2 && sid32[2 * i + 1] != 0) g_is64 = 0;
}
__global__ void k_bucket(const int* __restrict__ sid32) {
    int b = blockIdx.x * blockDim.x + threadIdx.x;
    if (b >= B_) return;
    int s = g_is64 ? sid32[2 * b] : sid32[b];
    int pos = atomicAdd(&g_count[s], 1);
    g_bucket[s][pos] = b;
}

__device__ __forceinline__ ushort4 split4(float4 v, ushort4* lo) {
    __nv_bfloat16 h0 = __float2bfloat16(v.x), h1 = __float2bfloat16(v.y);
    __nv_bfloat16 h2 = __float2bfloat16(v.z), h3 = __float2bfloat16(v.w);
    __nv_bfloat16 l0 = __float2bfloat16(v.x - __bfloat162float(h0));
    __nv_bfloat16 l1 = __float2bfloat16(v.y - __bfloat162float(h1));
    __nv_bfloat16 l2 = __float2bfloat16(v.z - __bfloat162float(h2));
    __nv_bfloat16 l3 = __float2bfloat16(v.w - __bfloat162float(h3));
    *lo = make_ushort4(__bfloat16_as_ushort(l0), __bfloat16_as_ushort(l1),
                       __bfloat16_as_ushort(l2), __bfloat16_as_ushort(l3));
    return make_ushort4(__bfloat16_as_ushort(h0), __bfloat16_as_ushort(h1),
                        __bfloat16_as_ushort(h2), __bfloat16_as_ushort(h3));
}

__global__ void k_convx(const float* __restrict__ x) {
    size_t i = (size_t)blockIdx.x * blockDim.x + threadIdx.x;
    ushort4 lo;
    ushort4 hi = split4(((const float4*)x)[i], &lo);
    ((ushort4*)g_xhi)[i] = hi;
    ((ushort4*)g_xlo)[i] = lo;
}
__global__ void k_convw(const float* __restrict__ w) {
    size_t i = (size_t)blockIdx.x * blockDim.x + threadIdx.x;
    ushort4 lo;
    ushort4 hi = split4(((const float4*)w)[i], &lo);
    ((ushort4*)g_whi)[i] = hi;
    ((ushort4*)g_wlo)[i] = lo;
}

// ---------------- GEMM -------------------------------------------------------
// smem stage layout (bytes): A rows padded 64->80, B rows padded 256->272 for
// conflict-free ldmatrix (row-to-row bank shifts 20 and 68 words, both giving
// distinct banks across any 8 consecutive rows).
static constexpr int STR_A   = 80;
static constexpr int STR_B   = 272;
static constexpr int OFF_AHI = 0;
static constexpr int OFF_ALO = 128 * STR_A;             // 10240
static constexpr int OFF_BHI = 2 * 128 * STR_A;         // 20480
static constexpr int OFF_BLO = OFF_BHI + TK * STR_B;    // 29184
static constexpr int SSTAGE  = OFF_BLO + TK * STR_B;    // 37888
static constexpr int SMEM_DYN = 2 * SSTAGE;             // 75776

__global__ __launch_bounds__(128)
void k_gemm(const float* __restrict__ bias, float* __restrict__ out) {
    const int s    = blockIdx.z;
    const int cnt  = g_count[s];
    const int row0 = blockIdx.y * TM;
    if (row0 >= cnt) return;
    const int col0 = blockIdx.x * TN;

    extern __shared__ char smem[];
    __shared__ int rowsm[TM];
    const uint32_t smb = smem_u32(smem);
    const int tid  = threadIdx.x;
    const int lane = tid & 31;
    const int wid  = tid >> 5;
    const int wm   = wid & 1;    // warp row  (x64)
    const int wn   = wid >> 1;   // warp col  (x64)

    if (tid < TM) {
        int r = row0 + tid;
        rowsm[tid] = (r < cnt) ? g_bucket[s][r] : -1;
    }
    __syncthreads();

    // ---- per-thread cp.async source/dest precomputation
    const int ar = tid >> 2, ac = tid & 3;          // A: 128 rows x 4 chunks
    size_t   aga[4];
    uint32_t asa[4];
#pragma unroll
    for (int l = 0; l < 4; l++) {
        int rr = ar + l * 32;
        int grow = rowsm[rr];
        if (grow < 0) grow = 0;
        aga[l] = (size_t)grow * IN_ + ac * 8;
        asa[l] = rr * STR_A + ac * 16;
    }
    const int bk = tid >> 4, bc = tid & 15;         // B: 32 rows x 16 chunks
    const size_t bgbase = (size_t)s * IN_ * OUT_ + col0 + bc * 8;
    uint32_t bsa[4];
#pragma unroll
    for (int l = 0; l < 4; l++) bsa[l] = (bk + l * 8) * STR_B + bc * 16;

    auto issue = [&](int st) {
        const int k0 = st * TK;
        const uint32_t sb = smb + (st & 1) * SSTAGE;
#pragma unroll
        for (int l = 0; l < 4; l++) {
            cpasync16(sb + OFF_AHI + asa[l], g_xhi + aga[l] + k0);
            cpasync16(sb + OFF_ALO + asa[l], g_xlo + aga[l] + k0);
        }
#pragma unroll
        for (int l = 0; l < 4; l++) {
            size_t g = bgbase + (size_t)(k0 + bk + l * 8) * OUT_;
            cpasync16(sb + OFF_BHI + bsa[l], g_whi + g);
            cpasync16(sb + OFF_BLO + bsa[l], g_wlo + g);
        }
        CP_COMMIT();
    };

    issue(0);
    issue(1);

    float acc[4][8][4];
#pragma unroll
    for (int i = 0; i < 4; i++)
#pragma unroll
        for (int j = 0; j < 8; j++)
#pragma unroll
            for (int k = 0; k < 4; k++) acc[i][j][k] = 0.f;

    // ldmatrix per-thread address components
    const int a_row  = (lane & 15);          // m within 16-block
    const int a_coff = (lane >> 4) * 16;     // k-half byte offset
    const int b_krow = (lane & 7) + ((lane >> 3) & 1) * 8;
    const int b_noff = (lane >> 4) * 8;      // n-half

    for (int st = 0; st < NST; st++) {
        CP_WAIT1();
        __syncthreads();
        const uint32_t sb = smb + (st & 1) * SSTAGE;

#pragma unroll
        for (int kk = 0; kk < 2; kk++) {
            uint32_t Ah[4][4], Al[4][4], Bh[4][4], Bl[4][4];
#pragma unroll
            for (int mi = 0; mi < 4; mi++) {
                uint32_t ad = sb + OFF_AHI +
                    (wm * 64 + mi * 16 + a_row) * STR_A + kk * 32 + a_coff;
                LDSM_X4(Ah[mi], ad);
                LDSM_X4(Al[mi], ad + (OFF_ALO - OFF_AHI));
            }
#pragma unroll
            for (int bj = 0; bj < 4; bj++) {
                uint32_t bd = sb + OFF_BHI +
                    (kk * 16 + b_krow) * STR_B +
                    (wn * 64 + bj * 16 + b_noff) * 2;
                LDSM_X4_T(Bh[bj], bd);
                LDSM_X4_T(Bl[bj], bd + (OFF_BLO - OFF_BHI));
            }
            // three split passes: hi*hi, lo*hi, hi*lo (lo*lo dropped, ~2^-16)
#pragma unroll
            for (int mi = 0; mi < 4; mi++)
#pragma unroll
                for (int nj = 0; nj < 8; nj++) {
                    const int g = nj >> 1, o = (nj & 1) * 2;
                    MMA16816(acc[mi][nj], Ah[mi], Bh[g][o], Bh[g][o + 1]);
                    MMA16816(acc[mi][nj], Al[mi], Bh[g][o], Bh[g][o + 1]);
                    MMA16816(acc[mi][nj], Ah[mi], Bl[g][o], Bl[g][o + 1]);
                }
        }
        __syncthreads();
        if (st + 2 < NST) issue(st + 2);
        else CP_COMMIT();   // empty group keeps wait_group accounting uniform
    }

    // ---- epilogue: D[m][n] + bias
#pragma unroll
    for (int nj = 0; nj < 8; nj++) {
        const int col = col0 + wn * 64 + nj * 8 + (lane & 3) * 2;
        const float2 bv = *(const float2*)(bias + s * OUT_ + col);
#pragma unroll
        for (int mi = 0; mi < 4; mi++) {
            const int mr = wm * 64 + mi * 16 + (lane >> 2);
            const int g0 = rowsm[mr];
            const int g1 = rowsm[mr + 8];
            if (g0 >= 0) {
                float2 v = make_float2(acc[mi][nj][0] + bv.x,
                                       acc[mi][nj][1] + bv.y);
                *(float2*)(out + (size_t)g0 * OUT_ + col) = v;
            }
            if (g1 >= 0) {
                float2 v = make_float2(acc[mi][nj][2] + bv.x,
                                       acc[mi][nj][3] + bv.y);
                *(float2*)(out + (size_t)g1 * OUT_ + col) = v;
            }
        }
    }
}

// ---------------- launch -----------------------------------------------------
extern "C" void kernel_launch(void* const* d_in, const int* in_sizes, int n_in,
                              void* d_out, int out_size) {
    const float* x    = (const float*)d_in[0];
    const int*   sid  = (const int*)d_in[1];
    const float* w    = (const float*)d_in[2];
    const float* bias = (const float*)d_in[3];
    float*       out  = (float*)d_out;

    k_init<<<1, 32>>>();
    k_detect<<<(B_ / 2 + 255) / 256, 256>>>(sid);
    k_bucket<<<(B_ + 255) / 256, 256>>>(sid);
    k_convx<<<(B_ * IN_ / 4) / 256, 256>>>(x);
    k_convw<<<((size_t)S_ * IN_ * OUT_ / 4) / 256, 256>>>(w);

    cudaFuncSetAttribute(k_gemm, cudaFuncAttributeMaxDynamicSharedMemorySize,
                         SMEM_DYN);
    dim3 grid(OUT_ / TN, B_ / TM, S_);
    k_gemm<<<grid, 128, SMEM_DYN>>>(bias, out);
}

// round 6
// speedup vs baseline: 6.0925x; 2.1292x over previous
#include <cuda_runtime.h>
#include <cuda_fp16.h>
#include <cstdint>

#define B_   8192
#define IN_  2048
#define OUT_ 3072
#define S_   8

#define TM 128
#define TN 128
#define TK 32
#define NST (IN_ / TK)   // 64 K-stages
#define NBUF 3

// ---------------- scratch (device globals; no cudaMalloc allowed) -----------
__device__ int g_bucket[S_][B_];
__device__ int g_count[S_];
__device__ int g_is64;

__device__ __half g_xf16[(size_t)B_ * IN_];
__device__ __half g_wf16[(size_t)S_ * IN_ * OUT_];   // [s][k][o]

// ---------------- helpers ----------------------------------------------------
__device__ __forceinline__ uint32_t smem_u32(const void* p) {
    uint32_t a;
    asm("{ .reg .u64 t; cvta.to.shared.u64 t, %1; cvt.u32.u64 %0, t; }"
        : "=r"(a) : "l"(p));
    return a;
}
__device__ __forceinline__ void cpasync16(uint32_t s, const void* g) {
    asm volatile("cp.async.cg.shared.global [%0], [%1], 16;"
                 :: "r"(s), "l"(g) : "memory");
}
#define CP_COMMIT() asm volatile("cp.async.commit_group;" ::: "memory")
#define CP_WAIT2()  asm volatile("cp.async.wait_group 2;"  ::: "memory")

#define LDSM_X4(r, a)                                                            \
    asm volatile("ldmatrix.sync.aligned.m8n8.x4.shared.b16 {%0,%1,%2,%3}, [%4];" \
                 : "=r"((r)[0]), "=r"((r)[1]), "=r"((r)[2]), "=r"((r)[3])        \
                 : "r"(a))
#define LDSM_X4_T(r, a)                                                          \
    asm volatile("ldmatrix.sync.aligned.m8n8.x4.trans.shared.b16 {%0,%1,%2,%3}, [%4];" \
                 : "=r"((r)[0]), "=r"((r)[1]), "=r"((r)[2]), "=r"((r)[3])        \
                 : "r"(a))

#define MMA16816(d, a, b0, b1)                                               \
    asm volatile("mma.sync.aligned.m16n8k16.row.col.f32.f16.f16.f32 "        \
                 "{%0,%1,%2,%3}, {%4,%5,%6,%7}, {%8,%9}, {%0,%1,%2,%3};"     \
                 : "+f"((d)[0]), "+f"((d)[1]), "+f"((d)[2]), "+f"((d)[3])    \
                 : "r"((a)[0]), "r"((a)[1]), "r"((a)[2]), "r"((a)[3]),       \
                   "r"(b0), "r"(b1))

// ---------------- prologue kernels -------------------------------------------
__global__ void k_init() {
    if (threadIdx.x < S_) g_count[threadIdx.x] = 0;
    if (threadIdx.x == 0) g_is64 = 1;
}
__global__ void k_detect(const int* __restrict__ sid32) {
    int i = blockIdx.x * blockDim.x + threadIdx.x;
    if (i < B_ / 2 && sid32[2 * i + 1] != 0) g_is64 = 0;
}
__global__ void k_bucket(const int* __restrict__ sid32) {
    int b = blockIdx.x * blockDim.x + threadIdx.x;
    if (b >= B_) return;
    int s = g_is64 ? sid32[2 * b] : sid32[b];
    int pos = atomicAdd(&g_count[s], 1);
    g_bucket[s][pos] = b;
}

__device__ __forceinline__ uint2 conv4(float4 v) {
    __half2 a = __floats2half2_rn(v.x, v.y);
    __half2 b = __floats2half2_rn(v.z, v.w);
    uint2 r;
    r.x = *reinterpret_cast<uint32_t*>(&a);
    r.y = *reinterpret_cast<uint32_t*>(&b);
    return r;
}
__global__ void k_convx(const float* __restrict__ x) {
    size_t i = (size_t)blockIdx.x * blockDim.x + threadIdx.x;
    ((uint2*)g_xf16)[i] = conv4(((const float4*)x)[i]);
}
__global__ void k_convw(const float* __restrict__ w) {
    size_t i = (size_t)blockIdx.x * blockDim.x + threadIdx.x;
    ((uint2*)g_wf16)[i] = conv4(((const float4*)w)[i]);
}

// ---------------- GEMM -------------------------------------------------------
// smem per stage: A 128 rows x 64B (pad to 80B), B 32 rows x 256B (pad 272B).
static constexpr int STR_A  = 80;
static constexpr int STR_B  = 272;
static constexpr int OFF_A  = 0;
static constexpr int OFF_B  = 128 * STR_A;            // 10240
static constexpr int SSTAGE = OFF_B + TK * STR_B;     // 18944
static constexpr int SMEM_DYN = NBUF * SSTAGE;        // 56832

__global__ __launch_bounds__(128)
void k_gemm(const float* __restrict__ bias, float* __restrict__ out) {
    const int s    = blockIdx.z;
    const int cnt  = g_count[s];
    const int row0 = blockIdx.y * TM;
    if (row0 >= cnt) return;
    const int col0 = blockIdx.x * TN;

    extern __shared__ char smem[];
    __shared__ int rowsm[TM];
    const uint32_t smb = smem_u32(smem);
    const int tid  = threadIdx.x;
    const int lane = tid & 31;
    const int wid  = tid >> 5;
    const int wm   = wid & 1;    // warp row (x64)
    const int wn   = wid >> 1;   // warp col (x64)

    if (tid < TM) {
        int r = row0 + tid;
        rowsm[tid] = (r < cnt) ? g_bucket[s][r] : -1;
    }
    __syncthreads();

    // cp.async addressing: A 128 rows x 4 chunks of 16B; B 32 rows x 16 chunks
    const int ar = tid >> 2, ac = tid & 3;
    size_t   aga[4];
    uint32_t asa[4];
#pragma unroll
    for (int l = 0; l < 4; l++) {
        int rr = ar + l * 32;
        int grow = rowsm[rr];
        if (grow < 0) grow = 0;
        aga[l] = (size_t)grow * IN_ + ac * 8;
        asa[l] = rr * STR_A + ac * 16;
    }
    const int bk = tid >> 4, bc = tid & 15;
    const size_t bgbase = (size_t)s * IN_ * OUT_ + col0 + bc * 8;
    uint32_t bsa[4];
#pragma unroll
    for (int l = 0; l < 4; l++) bsa[l] = (bk + l * 8) * STR_B + bc * 16;

    auto issue = [&](int st) {
        const int k0 = st * TK;
        const uint32_t sb = smb + (st % NBUF) * SSTAGE;
#pragma unroll
        for (int l = 0; l < 4; l++)
            cpasync16(sb + OFF_A + asa[l], g_xf16 + aga[l] + k0);
#pragma unroll
        for (int l = 0; l < 4; l++) {
            size_t g = bgbase + (size_t)(k0 + bk + l * 8) * OUT_;
            cpasync16(sb + OFF_B + bsa[l], g_wf16 + g);
        }
        CP_COMMIT();
    };

    issue(0);
    issue(1);
    issue(2);

    float acc[4][8][4];
#pragma unroll
    for (int i = 0; i < 4; i++)
#pragma unroll
        for (int j = 0; j < 8; j++)
#pragma unroll
            for (int k = 0; k < 4; k++) acc[i][j][k] = 0.f;

    const int a_row  = (lane & 15);
    const int a_coff = (lane >> 4) * 16;
    const int b_krow = (lane & 7) + ((lane >> 3) & 1) * 8;
    const int b_noff = (lane >> 4) * 8;

    for (int st = 0; st < NST; st++) {
        CP_WAIT2();
        __syncthreads();
        const uint32_t sb = smb + (st % NBUF) * SSTAGE;

#pragma unroll
        for (int kk = 0; kk < 2; kk++) {
            uint32_t A[4][4], Bf[4][4];
#pragma unroll
            for (int mi = 0; mi < 4; mi++) {
                uint32_t ad = sb + OFF_A +
                    (wm * 64 + mi * 16 + a_row) * STR_A + kk * 32 + a_coff;
                LDSM_X4(A[mi], ad);
            }
#pragma unroll
            for (int bj = 0; bj < 4; bj++) {
                uint32_t bd = sb + OFF_B +
                    (kk * 16 + b_krow) * STR_B +
                    (wn * 64 + bj * 16 + b_noff) * 2;
                LDSM_X4_T(Bf[bj], bd);
            }
#pragma unroll
            for (int mi = 0; mi < 4; mi++)
#pragma unroll
                for (int nj = 0; nj < 8; nj++) {
                    const int g = nj >> 1, o = (nj & 1) * 2;
                    MMA16816(acc[mi][nj], A[mi], Bf[g][o], Bf[g][o + 1]);
                }
        }
        __syncthreads();
        if (st + NBUF < NST) issue(st + NBUF);
        else CP_COMMIT();   // keep group accounting uniform
    }

    // ---- epilogue: D[m][n] + bias
#pragma unroll
    for (int nj = 0; nj < 8; nj++) {
        const int col = col0 + wn * 64 + nj * 8 + (lane & 3) * 2;
        const float2 bv = *(const float2*)(bias + s * OUT_ + col);
#pragma unroll
        for (int mi = 0; mi < 4; mi++) {
            const int mr = wm * 64 + mi * 16 + (lane >> 2);
            const int g0 = rowsm[mr];
            const int g1 = rowsm[mr + 8];
            if (g0 >= 0) {
                float2 v = make_float2(acc[mi][nj][0] + bv.x,
                                       acc[mi][nj][1] + bv.y);
                *(float2*)(out + (size_t)g0 * OUT_ + col) = v;
            }
            if (g1 >= 0) {
                float2 v = make_float2(acc[mi][nj][2] + bv.x,
                                       acc[mi][nj][3] + bv.y);
                *(float2*)(out + (size_t)g1 * OUT_ + col) = v;
            }
        }
    }
}

// ---------------- launch -----------------------------------------------------
extern "C" void kernel_launch(void* const* d_in, const int* in_sizes, int n_in,
                              void* d_out, int out_size) {
    const float* x    = (const float*)d_in[0];
    const int*   sid  = (const int*)d_in[1];
    const float* w    = (const float*)d_in[2];
    const float* bias = (const float*)d_in[3];
    float*       out  = (float*)d_out;

    k_init<<<1, 32>>>();
    k_detect<<<(B_ / 2 + 255) / 256, 256>>>(sid);
    k_bucket<<<(B_ + 255) / 256, 256>>>(sid);
    k_convx<<<(B_ * IN_ / 4) / 256, 256>>>(x);
    k_convw<<<((size_t)S_ * IN_ * OUT_ / 4) / 256, 256>>>(w);

    cudaFuncSetAttribute(k_gemm, cudaFuncAttributeMaxDynamicSharedMemorySize,
                         SMEM_DYN);
    dim3 grid(OUT_ / TN, B_ / TM, S_);
    k_gemm<<<grid, 128, SMEM_DYN>>>(bias, out);
}

// round 7
// speedup vs baseline: 6.4547x; 1.0594x over previous
#include <cuda_runtime.h>
#include <cuda_fp16.h>
#include <cstdint>

#define B_   8192
#define IN_  2048
#define OUT_ 3072
#define S_   8

#define TM 128
#define TN 128
#define TK 32
#define NST (IN_ / TK)   // 64 K-stages
#define NBUF 4

// ---------------- scratch (device globals; no cudaMalloc allowed) -----------
__device__ int g_bucket[S_][B_];
__device__ int g_count[S_];
__device__ int g_is64;

__device__ __half g_xf16[(size_t)B_ * IN_];
__device__ __half g_wf16[(size_t)S_ * IN_ * OUT_];   // [s][k][o]

// ---------------- helpers ----------------------------------------------------
__device__ __forceinline__ uint32_t smem_u32(const void* p) {
    uint32_t a;
    asm("{ .reg .u64 t; cvta.to.shared.u64 t, %1; cvt.u32.u64 %0, t; }"
        : "=r"(a) : "l"(p));
    return a;
}
__device__ __forceinline__ void cpasync16(uint32_t s, const void* g) {
    asm volatile("cp.async.cg.shared.global [%0], [%1], 16;"
                 :: "r"(s), "l"(g) : "memory");
}
#define CP_COMMIT() asm volatile("cp.async.commit_group;" ::: "memory")
#define CP_WAIT3()  asm volatile("cp.async.wait_group 3;"  ::: "memory")

#define LDSM_X4(r, a)                                                            \
    asm volatile("ldmatrix.sync.aligned.m8n8.x4.shared.b16 {%0,%1,%2,%3}, [%4];" \
                 : "=r"((r)[0]), "=r"((r)[1]), "=r"((r)[2]), "=r"((r)[3])        \
                 : "r"(a))
#define LDSM_X4_T(r, a)                                                          \
    asm volatile("ldmatrix.sync.aligned.m8n8.x4.trans.shared.b16 {%0,%1,%2,%3}, [%4];" \
                 : "=r"((r)[0]), "=r"((r)[1]), "=r"((r)[2]), "=r"((r)[3])        \
                 : "r"(a))

#define MMA16816(d, a, b0, b1)                                               \
    asm volatile("mma.sync.aligned.m16n8k16.row.col.f32.f16.f16.f32 "        \
                 "{%0,%1,%2,%3}, {%4,%5,%6,%7}, {%8,%9}, {%0,%1,%2,%3};"     \
                 : "+f"((d)[0]), "+f"((d)[1]), "+f"((d)[2]), "+f"((d)[3])    \
                 : "r"((a)[0]), "r"((a)[1]), "r"((a)[2]), "r"((a)[3]),       \
                   "r"(b0), "r"(b1))

// ---------------- prologue kernels -------------------------------------------
__global__ void k_init() {
    if (threadIdx.x < S_) g_count[threadIdx.x] = 0;
    if (threadIdx.x == 0) g_is64 = 1;
}
__global__ void k_detect(const int* __restrict__ sid32) {
    int i = blockIdx.x * blockDim.x + threadIdx.x;
    if (i < B_ / 2 && sid32[2 * i + 1] != 0) g_is64 = 0;
}
__global__ void k_bucket(const int* __restrict__ sid32) {
    int b = blockIdx.x * blockDim.x + threadIdx.x;
    if (b >= B_) return;
    int s = g_is64 ? sid32[2 * b] : sid32[b];
    int pos = atomicAdd(&g_count[s], 1);
    g_bucket[s][pos] = b;
}

// Fused x+W fp32 -> fp16 conversion. One thread = 8 floats (two LDG.128, one STG.128).
static constexpr size_t XU = (size_t)B_ * IN_ / 8;            // 2M units
static constexpr size_t WU = (size_t)S_ * IN_ * OUT_ / 8;     // 6.29M units

__device__ __forceinline__ uint4 conv8(const float4* src) {
    float4 v0 = src[0], v1 = src[1];
    __half2 a = __floats2half2_rn(v0.x, v0.y);
    __half2 b = __floats2half2_rn(v0.z, v0.w);
    __half2 c = __floats2half2_rn(v1.x, v1.y);
    __half2 d = __floats2half2_rn(v1.z, v1.w);
    uint4 r;
    r.x = *reinterpret_cast<uint32_t*>(&a);
    r.y = *reinterpret_cast<uint32_t*>(&b);
    r.z = *reinterpret_cast<uint32_t*>(&c);
    r.w = *reinterpret_cast<uint32_t*>(&d);
    return r;
}

__global__ void k_conv(const float* __restrict__ x, const float* __restrict__ w) {
    size_t i = (size_t)blockIdx.x * blockDim.x + threadIdx.x;
    if (i < XU) {
        ((uint4*)g_xf16)[i] = conv8((const float4*)x + i * 2);
    } else {
        size_t j = i - XU;
        if (j < WU)
            ((uint4*)g_wf16)[j] = conv8((const float4*)w + j * 2);
    }
}

// ---------------- GEMM -------------------------------------------------------
// smem per stage: A 128 rows x 64B (pad to 80B), B 32 rows x 256B (pad 272B).
static constexpr int STR_A  = 80;
static constexpr int STR_B  = 272;
static constexpr int OFF_A  = 0;
static constexpr int OFF_B  = 128 * STR_A;            // 10240
static constexpr int SSTAGE = OFF_B + TK * STR_B;     // 18944
static constexpr int SMEM_DYN = NBUF * SSTAGE;        // 75776

__global__ __launch_bounds__(128)
void k_gemm(const float* __restrict__ bias, float* __restrict__ out) {
    const int s    = blockIdx.z;
    const int cnt  = g_count[s];
    const int row0 = blockIdx.y * TM;
    if (row0 >= cnt) return;
    const int col0 = blockIdx.x * TN;

    extern __shared__ char smem[];
    __shared__ int rowsm[TM];
    const uint32_t smb = smem_u32(smem);
    const int tid  = threadIdx.x;
    const int lane = tid & 31;
    const int wid  = tid >> 5;
    const int wm   = wid & 1;    // warp row (x64)
    const int wn   = wid >> 1;   // warp col (x64)

    if (tid < TM) {
        int r = row0 + tid;
        rowsm[tid] = (r < cnt) ? g_bucket[s][r] : -1;
    }
    __syncthreads();

    // cp.async addressing: A 128 rows x 4 chunks of 16B; B 32 rows x 16 chunks
    const int ar = tid >> 2, ac = tid & 3;
    size_t   aga[4];
    uint32_t asa[4];
#pragma unroll
    for (int l = 0; l < 4; l++) {
        int rr = ar + l * 32;
        int grow = rowsm[rr];
        if (grow < 0) grow = 0;
        aga[l] = (size_t)grow * IN_ + ac * 8;
        asa[l] = rr * STR_A + ac * 16;
    }
    const int bk = tid >> 4, bc = tid & 15;
    const size_t bgbase = (size_t)s * IN_ * OUT_ + col0 + bc * 8;
    uint32_t bsa[4];
#pragma unroll
    for (int l = 0; l < 4; l++) bsa[l] = (bk + l * 8) * STR_B + bc * 16;

    auto issue = [&](int st) {
        const int k0 = st * TK;
        const uint32_t sb = smb + (st % NBUF) * SSTAGE;
#pragma unroll
        for (int l = 0; l < 4; l++)
            cpasync16(sb + OFF_A + asa[l], g_xf16 + aga[l] + k0);
#pragma unroll
        for (int l = 0; l < 4; l++) {
            size_t g = bgbase + (size_t)(k0 + bk + l * 8) * OUT_;
            cpasync16(sb + OFF_B + bsa[l], g_wf16 + g);
        }
        CP_COMMIT();
    };

    issue(0);
    issue(1);
    issue(2);
    issue(3);

    float acc[4][8][4];
#pragma unroll
    for (int i = 0; i < 4; i++)
#pragma unroll
        for (int j = 0; j < 8; j++)
#pragma unroll
            for (int k = 0; k < 4; k++) acc[i][j][k] = 0.f;

    const int a_row  = (lane & 15);
    const int a_coff = (lane >> 4) * 16;
    const int b_krow = (lane & 7) + ((lane >> 3) & 1) * 8;
    const int b_noff = (lane >> 4) * 8;

    for (int st = 0; st < NST; st++) {
        CP_WAIT3();
        __syncthreads();
        const uint32_t sb = smb + (st % NBUF) * SSTAGE;

#pragma unroll
        for (int kk = 0; kk < 2; kk++) {
            uint32_t A[4][4], Bf[4][4];
#pragma unroll
            for (int mi = 0; mi < 4; mi++) {
                uint32_t ad = sb + OFF_A +
                    (wm * 64 + mi * 16 + a_row) * STR_A + kk * 32 + a_coff;
                LDSM_X4(A[mi], ad);
            }
#pragma unroll
            for (int bj = 0; bj < 4; bj++) {
                uint32_t bd = sb + OFF_B +
                    (kk * 16 + b_krow) * STR_B +
                    (wn * 64 + bj * 16 + b_noff) * 2;
                LDSM_X4_T(Bf[bj], bd);
            }
#pragma unroll
            for (int mi = 0; mi < 4; mi++)
#pragma unroll
                for (int nj = 0; nj < 8; nj++) {
                    const int g = nj >> 1, o = (nj & 1) * 2;
                    MMA16816(acc[mi][nj], A[mi], Bf[g][o], Bf[g][o + 1]);
                }
        }
        __syncthreads();
        if (st + NBUF < NST) issue(st + NBUF);
        else CP_COMMIT();   // keep group accounting uniform
    }

    // ---- epilogue: D[m][n] + bias
#pragma unroll
    for (int nj = 0; nj < 8; nj++) {
        const int col = col0 + wn * 64 + nj * 8 + (lane & 3) * 2;
        const float2 bv = *(const float2*)(bias + s * OUT_ + col);
#pragma unroll
        for (int mi = 0; mi < 4; mi++) {
            const int mr = wm * 64 + mi * 16 + (lane >> 2);
            const int g0 = rowsm[mr];
            const int g1 = rowsm[mr + 8];
            if (g0 >= 0) {
                float2 v = make_float2(acc[mi][nj][0] + bv.x,
                                       acc[mi][nj][1] + bv.y);
                *(float2*)(out + (size_t)g0 * OUT_ + col) = v;
            }
            if (g1 >= 0) {
                float2 v = make_float2(acc[mi][nj][2] + bv.x,
                                       acc[mi][nj][3] + bv.y);
                *(float2*)(out + (size_t)g1 * OUT_ + col) = v;
            }
        }
    }
}

// ---------------- launch -----------------------------------------------------
extern "C" void kernel_launch(void* const* d_in, const int* in_sizes, int n_in,
                              void* d_out, int out_size) {
    const float* x    = (const float*)d_in[0];
    const int*   sid  = (const int*)d_in[1];
    const float* w    = (const float*)d_in[2];
    const float* bias = (const float*)d_in[3];
    float*       out  = (float*)d_out;

    k_init<<<1, 32>>>();
    k_detect<<<(B_ / 2 + 255) / 256, 256>>>(sid);
    k_bucket<<<(B_ + 255) / 256, 256>>>(sid);
    k_conv<<<(int)((XU + WU + 255) / 256), 256>>>(x, w);

    cudaFuncSetAttribute(k_gemm, cudaFuncAttributeMaxDynamicSharedMemorySize,
                         SMEM_DYN);
    dim3 grid(OUT_ / TN, B_ / TM, S_);
    k_gemm<<<grid, 128, SMEM_DYN>>>(bias, out);
}